// round 2
// baseline (speedup 1.0000x reference)
#include <cuda_runtime.h>

#define NH 18
#define NP 9
#define RW 20   // padded weight-row width (floats) -> 80B, 16B-aligned rows

typedef unsigned long long u64;

// ---- smem float offsets (all multiples of 4 floats -> 16B aligned) ----
#define S_WF   0      // 6  rows x RW
#define S_WM   120    // 36 rows x RW
#define S_WUM  840    // 18 rows x RW (Wu rows 0..17, message part)
#define S_WUH  1200   // 18 rows x RW (Wu[18:36]+Wu[36:54] folded, since U==h there)
#define S_WR   1560   // 5 rows x RW
#define S_BF   1660
#define S_BM   1680
#define S_BU   1700
#define S_BR   1720
#define S_TOT  1728

__device__ __forceinline__ u64 dup2(float v){
    u64 r; asm("mov.b64 %0, {%1,%1};" : "=l"(r) : "f"(v)); return r;
}
__device__ __forceinline__ u64 pk2(float lo, float hi){
    u64 r; asm("mov.b64 %0, {%1,%2};" : "=l"(r) : "f"(lo), "f"(hi)); return r;
}
__device__ __forceinline__ void upk2(u64 v, float& lo, float& hi){
    asm("mov.b64 {%0,%1}, %2;" : "=f"(lo), "=f"(hi) : "l"(v));
}
__device__ __forceinline__ u64 fma2(u64 a, u64 b, u64 c){
    u64 d; asm("fma.rn.f32x2 %0, %1, %2, %3;" : "=l"(d) : "l"(a), "l"(b), "l"(c));
    return d;
}
__device__ __forceinline__ float tanhap(float x){
    float r; asm("tanh.approx.f32 %0, %1;" : "=f"(r) : "f"(x)); return r;
}

// load one padded 18-float weight row as 4x LDS.128 + 1x LDS.64 (broadcast)
__device__ __forceinline__ void ldrow(const float* s, int off, u64 w[NP]){
    const ulonglong2* p = (const ulonglong2*)(s + off);
    ulonglong2 q0 = p[0], q1 = p[1], q2 = p[2], q3 = p[3];
    w[0]=q0.x; w[1]=q0.y; w[2]=q1.x; w[3]=q1.y;
    w[4]=q2.x; w[5]=q2.y; w[6]=q3.x; w[7]=q3.y;
    w[8] = *(const u64*)(s + off + 16);
}

// h = tanh(x(6) @ Wf + bf)
__device__ __forceinline__ void layer1(const float xv[6], const float* s, float h[NH]){
    u64 acc[NP];
    const u64* b = (const u64*)(s + S_BF);
    #pragma unroll
    for (int p = 0; p < NP; p++) acc[p] = b[p];
    #pragma unroll
    for (int f = 0; f < 6; f++){
        u64 w[NP]; ldrow(s, S_WF + f*RW, w);
        u64 a = dup2(xv[f]);
        #pragma unroll
        for (int p = 0; p < NP; p++) acc[p] = fma2(a, w[p], acc[p]);
    }
    #pragma unroll
    for (int p = 0; p < NP; p++){
        float lo, hi; upk2(acc[p], lo, hi);
        h[2*p]   = tanhap(lo);
        h[2*p+1] = tanhap(hi);
    }
}

// M = tanh([hA, hB] @ Wm + bm)
__device__ __forceinline__ void mlayer(const float hA[NH], const float hB[NH],
                                       const float* s, float M[NH]){
    u64 acc[NP];
    const u64* b = (const u64*)(s + S_BM);
    #pragma unroll
    for (int p = 0; p < NP; p++) acc[p] = b[p];
    #pragma unroll
    for (int e = 0; e < NH; e++){
        u64 w[NP]; ldrow(s, S_WM + e*RW, w);
        u64 a = dup2(hA[e]);
        #pragma unroll
        for (int p = 0; p < NP; p++) acc[p] = fma2(a, w[p], acc[p]);
    }
    #pragma unroll
    for (int e = 0; e < NH; e++){
        u64 w[NP]; ldrow(s, S_WM + (NH+e)*RW, w);
        u64 a = dup2(hB[e]);
        #pragma unroll
        for (int p = 0; p < NP; p++) acc[p] = fma2(a, w[p], acc[p]);
    }
    #pragma unroll
    for (int p = 0; p < NP; p++){
        float lo, hi; upk2(acc[p], lo, hi);
        M[2*p]   = tanhap(lo);
        M[2*p+1] = tanhap(hi);
    }
}

// U_node = tanh(Mprev @ WuM + h @ WuH + bu); racc += U_node . Wr[node]
__device__ __forceinline__ void ulayer(const float Mp[NH], const float h[NH],
                                       const float* s, int node, u64& racc){
    u64 acc[NP];
    const u64* b = (const u64*)(s + S_BU);
    #pragma unroll
    for (int p = 0; p < NP; p++) acc[p] = b[p];
    #pragma unroll
    for (int e = 0; e < NH; e++){
        u64 w[NP]; ldrow(s, S_WUM + e*RW, w);
        u64 a = dup2(Mp[e]);
        #pragma unroll
        for (int p = 0; p < NP; p++) acc[p] = fma2(a, w[p], acc[p]);
    }
    #pragma unroll
    for (int e = 0; e < NH; e++){
        u64 w[NP]; ldrow(s, S_WUH + e*RW, w);
        u64 a = dup2(h[e]);
        #pragma unroll
        for (int p = 0; p < NP; p++) acc[p] = fma2(a, w[p], acc[p]);
    }
    u64 wr[NP]; ldrow(s, S_WR + node*RW, wr);
    #pragma unroll
    for (int p = 0; p < NP; p++){
        float lo, hi; upk2(acc[p], lo, hi);
        u64 u2 = pk2(tanhap(lo), tanhap(hi));
        racc = fma2(u2, wr[p], racc);
    }
}

__device__ __forceinline__ void loadx(const float* xb, int node, float xv[6]){
    const float2* p = (const float2*)(xb + node*6);   // 8B-aligned (b*120 + 24k)
    float2 a = p[0], c = p[1], d = p[2];
    xv[0]=a.x; xv[1]=a.y; xv[2]=c.x; xv[3]=c.y; xv[4]=d.x; xv[5]=d.y;
}

__global__ void __launch_bounds__(128, 3) mp_kernel(
    const float* __restrict__ x,
    const float* __restrict__ Wf, const float* __restrict__ bf,
    const float* __restrict__ Wm, const float* __restrict__ bm,
    const float* __restrict__ Wu, const float* __restrict__ bu,
    const float* __restrict__ Wr, const float* __restrict__ br,
    float* __restrict__ out, int n)
{
    __shared__ __align__(16) float s[S_TOT];
    const int t = threadIdx.x;
    for (int k = t; k < 6*NH;  k += 128){ int r=k/NH, c=k%NH; s[S_WF + r*RW + c] = Wf[k]; }
    for (int k = t; k < 36*NH; k += 128){ int r=k/NH, c=k%NH; s[S_WM + r*RW + c] = Wm[k]; }
    for (int k = t; k < 18*NH; k += 128){
        int r=k/NH, c=k%NH;
        s[S_WUM + r*RW + c] = Wu[k];
        s[S_WUH + r*RW + c] = Wu[324 + k] + Wu[648 + k];   // fold h-dup columns
    }
    for (int k = t; k < 90; k += 128){ int r=k/NH, c=k%NH; s[S_WR + r*RW + c] = Wr[k]; }
    if (t < NH){ s[S_BF+t] = bf[t]; s[S_BM+t] = bm[t]; s[S_BU+t] = bu[t]; }
    if (t == 0) s[S_BR] = br[0];
    __syncthreads();

    const int b = blockIdx.x * 128 + t;
    if (b >= n) return;

    const float* xb = x + (long long)b * 30;

    float hz[NH];            // h0 (kept live for M4, U0)
    float hbuf[2][NH];       // rolling h_i : hbuf[i & 1]
    float Mbuf[2][NH];       // rolling M_i : Mbuf[i & 1]
    float xv[6];

    loadx(xb, 0, xv);  layer1(xv, s, hz);         // h0
    loadx(xb, 1, xv);  layer1(xv, s, hbuf[1]);    // h1
    mlayer(hz, hbuf[1], s, Mbuf[0]);              // M0

    u64 racc = 0;   // packed (0.0f, 0.0f)
    #pragma unroll
    for (int i = 1; i <= 3; i++){
        loadx(xb, i+1, xv);
        layer1(xv, s, hbuf[(i+1)&1]);                       // h_{i+1}
        mlayer(hbuf[i&1], hbuf[(i+1)&1], s, Mbuf[i&1]);     // M_i
        ulayer(Mbuf[(i-1)&1], hbuf[i&1], s, i, racc);       // U_i (M_{i-1}, h_i)
    }
    mlayer(hbuf[0], hz, s, Mbuf[0]);              // M4 = (h4, h0)
    ulayer(Mbuf[1], hbuf[0], s, 4, racc);         // U4 (M3, h4)
    ulayer(Mbuf[0], hz,      s, 0, racc);         // U0 (M4, h0)

    float r0, r1; upk2(racc, r0, r1);
    out[b] = r0 + r1 + s[S_BR];
}

extern "C" void kernel_launch(void* const* d_in, const int* in_sizes, int n_in,
                              void* d_out, int out_size)
{
    const float* x  = (const float*)d_in[0];
    const float* Wf = (const float*)d_in[1];
    const float* bf = (const float*)d_in[2];
    const float* Wm = (const float*)d_in[3];
    const float* bm = (const float*)d_in[4];
    const float* Wu = (const float*)d_in[5];
    const float* bu = (const float*)d_in[6];
    const float* Wr = (const float*)d_in[7];
    const float* br = (const float*)d_in[8];
    float* out = (float*)d_out;

    const int n = in_sizes[0] / 30;     // B  (x is [B,5,6])
    const int blocks = (n + 127) / 128;
    mp_kernel<<<blocks, 128>>>(x, Wf, bf, Wm, bm, Wu, bu, Wr, br, out, n);
}

// round 3
// speedup vs baseline: 13.8876x; 13.8876x over previous
#include <cuda_runtime.h>

#define NH 18
#define NP 9
#define RW 20   // padded row width (floats) = 80B; 80 % 16 == 0 -> rows 16B-aligned

typedef unsigned long long u64;

// ---- smem float offsets (row bases all 16B-aligned) ----
#define S_WF   0      // 6  rows
#define S_WM   120    // 36 rows
#define S_WUM  840    // 18 rows (Wu rows 0..17, message part)
#define S_WUH  1200   // 18 rows (Wu[18:36]+Wu[36:54] folded, U==h there)
#define S_WR   1560   // 5 rows
#define S_BF   1660
#define S_BM   1680
#define S_BU   1700
#define S_BR   1720
#define S_TOT  1728

__device__ __forceinline__ u64 dup2(float v){
    u64 r; asm("mov.b64 %0, {%1,%1};" : "=l"(r) : "f"(v)); return r;
}
__device__ __forceinline__ u64 pk2(float lo, float hi){
    u64 r; asm("mov.b64 %0, {%1,%2};" : "=l"(r) : "f"(lo), "f"(hi)); return r;
}
__device__ __forceinline__ void upk2(u64 v, float& lo, float& hi){
    asm("mov.b64 {%0,%1}, %2;" : "=f"(lo), "=f"(hi) : "l"(v));
}
__device__ __forceinline__ u64 fma2(u64 a, u64 b, u64 c){
    u64 d; asm("fma.rn.f32x2 %0, %1, %2, %3;" : "=l"(d) : "l"(a), "l"(b), "l"(c));
    return d;
}
__device__ __forceinline__ float tanhap(float x){
    float r; asm("tanh.approx.f32 %0, %1;" : "=f"(r) : "f"(x)); return r;
}

// full 18-float row: 4x LDS.128 + 1x LDS.64 (broadcast, conflict-free)
__device__ __forceinline__ void ldrow9(const float* s, int off, u64 w[NP]){
    const ulonglong2* p = (const ulonglong2*)(s + off);
    ulonglong2 q0 = p[0], q1 = p[1];
    ulonglong2 q2 = ((const ulonglong2*)(s + off + 8))[0];
    w[0]=q0.x; w[1]=q0.y; w[2]=q1.x; w[3]=q1.y;
    w[4]=q2.x; w[5]=q2.y;
    ulonglong2 q3 = *(const ulonglong2*)(s + off + 12);
    w[6]=q3.x; w[7]=q3.y;
    w[8] = *(const u64*)(s + off + 16);
}
// pairs 0..3 (floats 0..7): 2x LDS.128
__device__ __forceinline__ void ldrowA(const float* s, int off, u64 w[4]){
    const ulonglong2* p = (const ulonglong2*)(s + off);
    ulonglong2 q0 = p[0], q1 = p[1];
    w[0]=q0.x; w[1]=q0.y; w[2]=q1.x; w[3]=q1.y;
}
// pairs 4..8 (floats 8..17): 2x LDS.128 + 1x LDS.64
__device__ __forceinline__ void ldrowB(const float* s, int off, u64 w[5]){
    const ulonglong2* p = (const ulonglong2*)(s + off + 8);
    ulonglong2 q0 = p[0], q1 = p[1];
    w[0]=q0.x; w[1]=q0.y; w[2]=q1.x; w[3]=q1.y;
    w[4] = *(const u64*)(s + off + 16);
}

__global__ void __launch_bounds__(128, 2) mp_kernel(
    const float* __restrict__ x,
    const float* __restrict__ Wf, const float* __restrict__ bf,
    const float* __restrict__ Wm, const float* __restrict__ bm,
    const float* __restrict__ Wu, const float* __restrict__ bu,
    const float* __restrict__ Wr, const float* __restrict__ br,
    float* __restrict__ out, int n)
{
    __shared__ __align__(16) float s[S_TOT];
    const int t = threadIdx.x;
    for (int k = t; k < 6*NH;  k += 128){ int r=k/NH, c=k%NH; s[S_WF + r*RW + c] = Wf[k]; }
    for (int k = t; k < 36*NH; k += 128){ int r=k/NH, c=k%NH; s[S_WM + r*RW + c] = Wm[k]; }
    for (int k = t; k < 18*NH; k += 128){
        int r=k/NH, c=k%NH;
        s[S_WUM + r*RW + c] = Wu[k];
        s[S_WUH + r*RW + c] = Wu[324 + k] + Wu[648 + k];   // fold duplicated h columns
    }
    for (int k = t; k < 90; k += 128){ int r=k/NH, c=k%NH; s[S_WR + r*RW + c] = Wr[k]; }
    if (t < NH){ s[S_BF+t] = bf[t]; s[S_BM+t] = bm[t]; s[S_BU+t] = bu[t]; }
    if (t == 0) s[S_BR] = br[0];
    __syncthreads();

    const int b = blockIdx.x * 128 + t;
    if (b >= n) return;

    // ---- x[b]: 30 floats, 8B-aligned ----
    float xv[30];
    {
        const float2* xb = (const float2*)(x + (long long)b * 30);
        #pragma unroll
        for (int k = 0; k < 15; k++){ float2 v = xb[k]; xv[2*k]=v.x; xv[2*k+1]=v.y; }
    }

    // ======== layer 1: h_i = tanh(x_i @ Wf + bf), all 5 nodes ========
    float h[5][NH];
    {
        u64 acc[5][NP];
        const u64* bb = (const u64*)(s + S_BF);
        #pragma unroll
        for (int p = 0; p < NP; p++){
            u64 bp = bb[p];
            #pragma unroll
            for (int i = 0; i < 5; i++) acc[i][p] = bp;
        }
        #pragma unroll
        for (int f = 0; f < 6; f++){
            u64 w[NP]; ldrow9(s, S_WF + f*RW, w);
            #pragma unroll
            for (int i = 0; i < 5; i++){
                u64 a = dup2(xv[i*6 + f]);
                #pragma unroll
                for (int p = 0; p < NP; p++) acc[i][p] = fma2(a, w[p], acc[i][p]);
            }
        }
        #pragma unroll
        for (int i = 0; i < 5; i++){
            #pragma unroll
            for (int p = 0; p < NP; p++){
                float lo, hi; upk2(acc[i][p], lo, hi);
                h[i][2*p]   = tanhap(lo);
                h[i][2*p+1] = tanhap(hi);
            }
        }
    }

    // ======== layer M: M_i = tanh([h_i, h_{i+1}] @ Wm + bm) ========
    float M[5][NH];
    {
        u64 acc[5][NP];
        const u64* bb = (const u64*)(s + S_BM);
        #pragma unroll
        for (int p = 0; p < NP; p++){
            u64 bp = bb[p];
            #pragma unroll
            for (int i = 0; i < 5; i++) acc[i][p] = bp;
        }
        #pragma unroll
        for (int e = 0; e < NH; e++){                     // rows [0,18): h_i
            u64 w[NP]; ldrow9(s, S_WM + e*RW, w);
            #pragma unroll
            for (int i = 0; i < 5; i++){
                u64 a = dup2(h[i][e]);
                #pragma unroll
                for (int p = 0; p < NP; p++) acc[i][p] = fma2(a, w[p], acc[i][p]);
            }
        }
        #pragma unroll
        for (int e = 0; e < NH; e++){                     // rows [18,36): h_{i+1}
            u64 w[NP]; ldrow9(s, S_WM + (NH+e)*RW, w);
            #pragma unroll
            for (int i = 0; i < 5; i++){
                u64 a = dup2(h[(i+1)%5][e]);
                #pragma unroll
                for (int p = 0; p < NP; p++) acc[i][p] = fma2(a, w[p], acc[i][p]);
            }
        }
        #pragma unroll
        for (int i = 0; i < 5; i++){
            #pragma unroll
            for (int p = 0; p < NP; p++){
                float lo, hi; upk2(acc[i][p], lo, hi);
                M[i][2*p]   = tanhap(lo);
                M[i][2*p+1] = tanhap(hi);
            }
        }
    }

    // ======== layer U + readout, channel-split two-pass ========
    // U_i = tanh(M_{i-1} @ WuM + h_i @ WuH + bu);  out += U_i . Wr[i]
    u64 racc = 0;  // packed (0,0)

    // ---- pass A: pairs 0..3 (channels 0..7) ----
    {
        u64 acc[5][4];
        const u64* bb = (const u64*)(s + S_BU);
        #pragma unroll
        for (int p = 0; p < 4; p++){
            u64 bp = bb[p];
            #pragma unroll
            for (int i = 0; i < 5; i++) acc[i][p] = bp;
        }
        #pragma unroll
        for (int e = 0; e < NH; e++){
            u64 w[4]; ldrowA(s, S_WUM + e*RW, w);
            #pragma unroll
            for (int i = 0; i < 5; i++){
                u64 a = dup2(M[(i+4)%5][e]);
                #pragma unroll
                for (int p = 0; p < 4; p++) acc[i][p] = fma2(a, w[p], acc[i][p]);
            }
        }
        #pragma unroll
        for (int e = 0; e < NH; e++){
            u64 w[4]; ldrowA(s, S_WUH + e*RW, w);
            #pragma unroll
            for (int i = 0; i < 5; i++){
                u64 a = dup2(h[i][e]);
                #pragma unroll
                for (int p = 0; p < 4; p++) acc[i][p] = fma2(a, w[p], acc[i][p]);
            }
        }
        #pragma unroll
        for (int i = 0; i < 5; i++){
            u64 wr[4]; ldrowA(s, S_WR + i*RW, wr);
            #pragma unroll
            for (int p = 0; p < 4; p++){
                float lo, hi; upk2(acc[i][p], lo, hi);
                u64 u2 = pk2(tanhap(lo), tanhap(hi));
                racc = fma2(u2, wr[p], racc);
            }
        }
    }

    // ---- pass B: pairs 4..8 (channels 8..17) ----
    {
        u64 acc[5][5];
        const u64* bb = (const u64*)(s + S_BU);
        #pragma unroll
        for (int p = 0; p < 5; p++){
            u64 bp = bb[4 + p];
            #pragma unroll
            for (int i = 0; i < 5; i++) acc[i][p] = bp;
        }
        #pragma unroll
        for (int e = 0; e < NH; e++){
            u64 w[5]; ldrowB(s, S_WUM + e*RW, w);
            #pragma unroll
            for (int i = 0; i < 5; i++){
                u64 a = dup2(M[(i+4)%5][e]);
                #pragma unroll
                for (int p = 0; p < 5; p++) acc[i][p] = fma2(a, w[p], acc[i][p]);
            }
        }
        #pragma unroll
        for (int e = 0; e < NH; e++){
            u64 w[5]; ldrowB(s, S_WUH + e*RW, w);
            #pragma unroll
            for (int i = 0; i < 5; i++){
                u64 a = dup2(h[i][e]);
                #pragma unroll
                for (int p = 0; p < 5; p++) acc[i][p] = fma2(a, w[p], acc[i][p]);
            }
        }
        #pragma unroll
        for (int i = 0; i < 5; i++){
            u64 wr[5]; ldrowB(s, S_WR + i*RW, wr);
            #pragma unroll
            for (int p = 0; p < 5; p++){
                float lo, hi; upk2(acc[i][p], lo, hi);
                u64 u2 = pk2(tanhap(lo), tanhap(hi));
                racc = fma2(u2, wr[p], racc);
            }
        }
    }

    float r0, r1; upk2(racc, r0, r1);
    out[b] = r0 + r1 + s[S_BR];
}

extern "C" void kernel_launch(void* const* d_in, const int* in_sizes, int n_in,
                              void* d_out, int out_size)
{
    const float* x  = (const float*)d_in[0];
    const float* Wf = (const float*)d_in[1];
    const float* bf = (const float*)d_in[2];
    const float* Wm = (const float*)d_in[3];
    const float* bm = (const float*)d_in[4];
    const float* Wu = (const float*)d_in[5];
    const float* bu = (const float*)d_in[6];
    const float* Wr = (const float*)d_in[7];
    const float* br = (const float*)d_in[8];
    float* out = (float*)d_out;

    const int n = in_sizes[0] / 30;   // B (x is [B,5,6])
    const int blocks = (n + 127) / 128;
    mp_kernel<<<blocks, 128>>>(x, Wf, bf, Wm, bm, Wu, bu, Wr, br, out, n);
}